// round 16
// baseline (speedup 1.0000x reference)
#include <cuda_runtime.h>
#include <cstdint>

// Problem constants (fixed by reference setup_inputs)
#define BB   16
#define NN   1000
#define KK   50
#define DD   128
#define NTHREADS 256
#define WPB  8            // warps (= nodes) per block
#define CAND_CAP 224      // per-warp candidate buffer (mc typically ~100)

// Output layout (float32, concatenation of reference outputs):
//   [0,        2048000)   x = init_embeddings
//   [2048000,  2848000)   edge_index row 0 (src)
//   [2848000,  3648000)   edge_index row 1 (dst)
//   [3648000, 106048000)  edge_emb [B*n*k, D]
#define X_ELEMS   (BB * NN * DD)
#define E_ELEMS   (BB * NN * KK)

#define FULLMASK 0xFFFFFFFFu

__global__ __launch_bounds__(NTHREADS, 6)
void tsp_topk_kernel(const float* __restrict__ locs,   // [B, N, 2]
                     const float* __restrict__ xin,    // [B, N, 128]
                     const float* __restrict__ W,      // [128]
                     const float* __restrict__ bias,   // [128]
                     float* __restrict__ out)
{
    __shared__ __align__(16) float2 sloc[1024];            // 8192 B (pads = huge)
    __shared__ unsigned int hist[WPB][256];                // 8 KB (per-warp)
    __shared__ unsigned long long cand[WPB][CAND_CAP];     // 14 KB (per-warp)
    __shared__ float        sdist[WPB][KK];                // 1.6 KB
    __shared__ unsigned int snbr [WPB][KK];                // 1.6 KB

    const int tid  = threadIdx.x;
    const int lane = tid & 31;
    const int wid  = tid >> 5;
    const int b    = blockIdx.x / (NN / WPB);   // 125 blocks per batch, exact
    const int node = blockIdx.x * WPB + wid;    // global node index b*NN + i
    const int i    = node - b * NN;

    // x output first: keeps DRAM busy during the selection phase. Streaming
    // read (__ldcs): xin is read exactly once, don't let it churn L2.
    reinterpret_cast<float4*>(out)[(size_t)node * 32 + lane] =
        __ldcs(reinterpret_cast<const float4*>(xin) + (size_t)node * 32 + lane);

    // Stage this batch's locations (float4 = 2 points/load); pad slots
    // 1000..1023 get huge coords (huge finite exponent bin, never selected).
    // The only block-wide barrier in the kernel.
    {
        const float4* l4 = reinterpret_cast<const float4*>(locs + (size_t)b * NN * 2);
        float4*       s4 = reinterpret_cast<float4*>(sloc);
        const float4  big = make_float4(2e9f, 2e9f, 2e9f, 2e9f);
        for (int t = tid; t < 512; t += NTHREADS)
            s4[t] = (t < 500) ? l4[t] : big;
    }
    #pragma unroll
    for (int j = 0; j < 8; ++j) hist[wid][lane * 8 + j] = 0;
    __syncthreads();

    const float2 my = sloc[i];
    const float4* s4loc = reinterpret_cast<const float4*>(sloc);

    // d^2 bits (monotone key: d^2 > 0 so float bits order == value order).
    // NO predicates: self (d^2 = 1e-12, the global min) and pads are included
    // and compensated structurally (rank target KK+1; filter drops self).
    // Matches jax f32 arithmetic exactly (no fma contraction).
    #define D2BITS(px, py, v)                                                 \
        do {                                                                  \
            float dx = my.x - (px);                                           \
            float dy = my.y - (py);                                           \
            float d2 = __fadd_rn(__fadd_rn(__fmul_rn(dx, dx),                 \
                                           __fmul_rn(dy, dy)), 1e-12f);       \
            (v) = __float_as_uint(d2);                                        \
        } while (0)

    // ---- Pass A: level-1 histogram on the 8-bit exponent. ONE pair-packed
    // match_any per float4 (a matched group shares BOTH exponents, so the
    // leader credits both bins) — halves the match_any count vs per-point
    // matching while producing the identical histogram. ----
    #pragma unroll 4
    for (int j = 0; j < 16; ++j) {
        const float4 p = s4loc[lane + 32 * j];
        unsigned int v0, v1;
        D2BITS(p.x, p.y, v0);
        D2BITS(p.z, p.w, v1);
        const unsigned int e0 = v0 >> 23;
        const unsigned int e1 = v1 >> 23;
        const unsigned int pair = (e0 << 8) | e1;
        const unsigned int mm   = __match_any_sync(FULLMASK, pair);
        if (lane == __ffs(mm) - 1) {
            const unsigned int c = __popc(mm);
            atomicAdd(&hist[wid][e0], c);
            atomicAdd(&hist[wid][e1], c);
        }
    }
    __syncwarp();

    // ---- Level-1 cutoff: bin of the (KK+1)-th smallest value INCLUDING the
    // self point (self is the global min, so rank KK+1 of all == rank KK of
    // the real neighbors; superset property preserved even under ties). ----
    const unsigned int KT = KK + 1;
    unsigned int c1, less1;
    {
        unsigned int h[8], s = 0;
        #pragma unroll
        for (int j = 0; j < 8; ++j) { h[j] = hist[wid][lane * 8 + j]; s += h[j]; }
        unsigned int incl = s;
        #pragma unroll
        for (int o = 1; o < 32; o <<= 1) {
            unsigned int x = __shfl_up_sync(FULLMASK, incl, o);
            if (lane >= o) incl += x;
        }
        const unsigned int e   = incl - s;
        const bool         has = (e < KT && KT <= incl);   // exactly one lane
        unsigned int cc = 0, ll = 0;
        if (has) {
            unsigned int cum = e;
            #pragma unroll
            for (int j = 0; j < 8; ++j) {
                if (KT <= cum + h[j]) { cc = lane * 8 + j; ll = cum; break; }
                cum += h[j];
            }
        }
        const int srcl = __ffs(__ballot_sync(FULLMASK, has)) - 1;
        c1    = __shfl_sync(FULLMASK, cc, srcl);
        less1 = __shfl_sync(FULLMASK, ll, srcl);
    }

    // ---- Pass B (fused): compact ALL items with exponent <= c1 into cand as
    // d^2-keys (u64: (d2bits<<10)|idx) AND build the level-2 histogram (next
    // 8 mantissa bits) for exponent == c1. Buffer order is immaterial (final
    // order comes from exact-key ranking), so both points of a lane share one
    // combined position assignment. ----
    #pragma unroll
    for (int j = 0; j < 8; ++j) hist[wid][lane * 8 + j] = 0;
    __syncwarp();
    unsigned int cnt = 0;
    #pragma unroll 4
    for (int j = 0; j < 16; ++j) {
        const int    q  = lane + 32 * j;
        const float4 p  = s4loc[q];
        const int    t0 = 2 * q;
        unsigned int v0, v1;
        D2BITS(p.x, p.y, v0);
        D2BITS(p.z, p.w, v1);

        const unsigned int e0 = v0 >> 23;
        const unsigned int e1 = v1 >> 23;
        if (e0 == c1) atomicAdd(&hist[wid][(v0 >> 15) & 0xFFu], 1u);
        if (e1 == c1) atomicAdd(&hist[wid][(v1 >> 15) & 0xFFu], 1u);

        const bool sel0 = (e0 <= c1);
        const bool sel1 = (e1 <= c1);
        const unsigned int m0 = __ballot_sync(FULLMASK, sel0);
        const unsigned int m1 = __ballot_sync(FULLMASK, sel1);
        const unsigned int below = (1u << lane) - 1u;
        if (sel0) {
            unsigned int pos = cnt + __popc(m0 & below);
            if (pos < CAND_CAP)
                cand[wid][pos] = ((unsigned long long)v0 << 10) | (unsigned)t0;
        }
        if (sel1) {
            unsigned int pos = cnt + __popc(m0) + __popc(m1 & below);
            if (pos < CAND_CAP)
                cand[wid][pos] = ((unsigned long long)v1 << 10)
                                 | (unsigned)(t0 + 1);
        }
        cnt += __popc(m0) + __popc(m1);
    }
    const unsigned int mc = min(cnt, (unsigned)CAND_CAP);
    __syncwarp();

    // ---- Level-2 cutoff -> 16-bit prefix P (rank KT within the combined
    // multiset); +1 sub-bin guard band captures every sqrt-rounding tie at
    // the boundary. ----
    unsigned int Pp1;
    {
        const unsigned int K2 = KT - less1;                // >= 1
        unsigned int h[8], s = 0;
        #pragma unroll
        for (int j = 0; j < 8; ++j) { h[j] = hist[wid][lane * 8 + j]; s += h[j]; }
        unsigned int incl = s;
        #pragma unroll
        for (int o = 1; o < 32; o <<= 1) {
            unsigned int x = __shfl_up_sync(FULLMASK, incl, o);
            if (lane >= o) incl += x;
        }
        const unsigned int e   = incl - s;
        const bool         has = (e < K2 && K2 <= incl);
        unsigned int pp = 0;
        if (has) {
            unsigned int cum = e;
            #pragma unroll
            for (int j = 0; j < 8; ++j) {
                if (K2 <= cum + h[j]) { pp = (c1 << 8) | (lane * 8 + j); break; }
                cum += h[j];
            }
        }
        const int srcl = __ffs(__ballot_sync(FULLMASK, has)) - 1;
        Pp1 = __shfl_sync(FULLMASK, pp, srcl) + 1;
    }

    // ---- In-place filter over the candidate buffer (~mc/32 iterations):
    // keep prefix <= Pp1 AND idx != i (drops the self point exactly once),
    // sqrt survivors, rewrite as the exact jax ordering key (bits(d)<<10)|idx
    // (ties break to lower index like lax.top_k). Safe in-place: ballot
    // converges the warp after all reads; writes never pass read frontier. ----
    unsigned int m = 0;
    for (unsigned int q0 = 0; q0 < mc; q0 += 32) {
        const unsigned int q = q0 + lane;
        unsigned long long key = 0;
        unsigned int v = 0;
        bool sel = false;
        if (q < mc) {
            key = cand[wid][q];
            v   = (unsigned int)(key >> 10);
            sel = ((v >> 15) <= Pp1) && ((unsigned)(key & 1023u) != (unsigned)i);
        }
        const unsigned int msk = __ballot_sync(FULLMASK, sel);
        if (sel) {
            float d = __fsqrt_rn(__uint_as_float(v));      // IEEE rn sqrt
            cand[wid][m + __popc(msk & ((1u << lane) - 1u))] =
                ((unsigned long long)__float_as_uint(d) << 10)
                | (unsigned)(key & 1023u);
        }
        m += __popc(msk);
    }
    __syncwarp();

    // ---- Rank-select: keys unique (idx in low bits) -> ranks are a
    // permutation; broadcast-LDS counting loop, no sort, no barriers. ----
    for (unsigned int q = lane; q < m; q += 32) {
        const unsigned long long mykey = cand[wid][q];
        unsigned int rk = 0;
        #pragma unroll 4
        for (unsigned int t = 0; t < m; ++t)
            rk += (cand[wid][t] < mykey);
        if (rk < KK) {
            sdist[wid][rk] = __uint_as_float((unsigned int)(mykey >> 10));
            snbr [wid][rk] = (unsigned int)(mykey & 1023u);
        }
    }
    __syncwarp();

    // W/bias loads issued before the edge_index stores so their L2 latency
    // hides under those stores.
    const float4 w4 = __ldg(reinterpret_cast<const float4*>(W) + lane);
    const float4 b4 = __ldg(reinterpret_cast<const float4*>(bias) + lane);

    // ---- edge_index (coalesced, as float). ----
    {
        float* srcp = out + X_ELEMS;
        float* dstp = srcp + E_ELEMS;
        const long long e0 = (long long)node * KK;
        #pragma unroll
        for (int s = lane; s < KK; s += 32) {
            srcp[e0 + s] = (float)node;
            dstp[e0 + s] = (float)(b * NN + (int)snbr[wid][s]);
        }
    }

    // ---- edge_emb[e, :] = dist_e * W + bias; 50 streaming STG.128 rows. ----
    float4* emb = reinterpret_cast<float4*>(out + X_ELEMS + 2LL * E_ELEMS);
    const long long base = (long long)node * KK;
    #pragma unroll 10
    for (int s = 0; s < KK; ++s) {
        const float dd = sdist[wid][s];
        float4 v;
        v.x = fmaf(dd, w4.x, b4.x);
        v.y = fmaf(dd, w4.y, b4.y);
        v.z = fmaf(dd, w4.z, b4.z);
        v.w = fmaf(dd, w4.w, b4.w);
        __stcs(emb + (base + s) * 32 + lane, v);
    }
    #undef D2BITS
}

extern "C" void kernel_launch(void* const* d_in, const int* in_sizes, int n_in,
                              void* d_out, int out_size)
{
    const float* locs = (const float*)d_in[0];   // [16, 1000, 2]
    const float* xin  = (const float*)d_in[1];   // [16, 1000, 128]
    const float* W    = (const float*)d_in[2];   // [1, 128]
    const float* bias = (const float*)d_in[3];   // [128]
    float* out = (float*)d_out;

    tsp_topk_kernel<<<(BB * NN) / WPB, NTHREADS, 0, 0>>>(locs, xin, W, bias, out);
}

// round 17
// speedup vs baseline: 1.0691x; 1.0691x over previous
#include <cuda_runtime.h>
#include <cstdint>

// Problem constants (fixed by reference setup_inputs)
#define BB   16
#define NN   1000
#define KK   50
#define DD   128
#define NTHREADS 256
#define WPB  8            // warps (= nodes) per block
#define CAND_CAP 224      // per-warp candidate buffer (mc typically ~100)

// Output layout (float32, concatenation of reference outputs):
//   [0,        2048000)   x = init_embeddings
//   [2048000,  2848000)   edge_index row 0 (src)
//   [2848000,  3648000)   edge_index row 1 (dst)
//   [3648000, 106048000)  edge_emb [B*n*k, D]
#define X_ELEMS   (BB * NN * DD)
#define E_ELEMS   (BB * NN * KK)

#define FULLMASK 0xFFFFFFFFu

__global__ __launch_bounds__(NTHREADS, 6)
void tsp_topk_kernel(const float* __restrict__ locs,   // [B, N, 2]
                     const float* __restrict__ xin,    // [B, N, 128]
                     const float* __restrict__ W,      // [128]
                     const float* __restrict__ bias,   // [128]
                     float* __restrict__ out)
{
    __shared__ __align__(16) float2 sloc[1024];            // 8192 B (pads = huge)
    __shared__ unsigned int hist[WPB][256];                // 8 KB (per-warp)
    __shared__ unsigned long long cand[WPB][CAND_CAP];     // 14 KB (per-warp)
    __shared__ float        sdist[WPB][KK];                // 1.6 KB
    __shared__ unsigned int snbr [WPB][KK];                // 1.6 KB

    const int tid  = threadIdx.x;
    const int lane = tid & 31;
    const int wid  = tid >> 5;
    const int b    = blockIdx.x / (NN / WPB);   // 125 blocks per batch, exact
    const int node = blockIdx.x * WPB + wid;    // global node index b*NN + i
    const int i    = node - b * NN;

    // x output first: keeps DRAM busy during the selection phase.
    reinterpret_cast<float4*>(out)[(size_t)node * 32 + lane] =
        reinterpret_cast<const float4*>(xin)[(size_t)node * 32 + lane];

    // Stage this batch's locations (float4 = 2 points/load); pad slots
    // 1000..1023 get huge coords (huge finite exponent bin, never selected).
    // The only block-wide barrier in the kernel.
    {
        const float4* l4 = reinterpret_cast<const float4*>(locs + (size_t)b * NN * 2);
        float4*       s4 = reinterpret_cast<float4*>(sloc);
        const float4  big = make_float4(2e9f, 2e9f, 2e9f, 2e9f);
        for (int t = tid; t < 512; t += NTHREADS)
            s4[t] = (t < 500) ? l4[t] : big;
    }
    #pragma unroll
    for (int j = 0; j < 8; ++j) hist[wid][lane * 8 + j] = 0;
    __syncthreads();

    const float2 my = sloc[i];
    const float4* s4loc = reinterpret_cast<const float4*>(sloc);

    // d^2 bits (monotone key: d^2 > 0 so float bits order == value order).
    // NO predicates: self (d^2 = 1e-12, the global min) and pads are included
    // and compensated structurally (rank target KK+1; filter drops self).
    // Matches jax f32 arithmetic exactly (no fma contraction).
    #define D2BITS(px, py, v)                                                 \
        do {                                                                  \
            float dx = my.x - (px);                                           \
            float dy = my.y - (py);                                           \
            float d2 = __fadd_rn(__fadd_rn(__fmul_rn(dx, dx),                 \
                                           __fmul_rn(dy, dy)), 1e-12f);       \
            (v) = __float_as_uint(d2);                                        \
        } while (0)

    // ---- Pass A: level-1 histogram on the 8-bit exponent. Unroll 4 batches
    // LDS.128s for MLP; per-warp hist; match_any aggregation (bins are
    // exponent-concentrated; per-point matching maximizes group size). ----
    #pragma unroll 4
    for (int j = 0; j < 16; ++j) {
        const float4 p = s4loc[lane + 32 * j];
        unsigned int v0, v1;
        D2BITS(p.x, p.y, v0);
        D2BITS(p.z, p.w, v1);
        unsigned int m0 = __match_any_sync(FULLMASK, v0 >> 23);
        if (lane == __ffs(m0) - 1) atomicAdd(&hist[wid][v0 >> 23], __popc(m0));
        unsigned int m1 = __match_any_sync(FULLMASK, v1 >> 23);
        if (lane == __ffs(m1) - 1) atomicAdd(&hist[wid][v1 >> 23], __popc(m1));
    }
    __syncwarp();

    // ---- Level-1 cutoff: bin of the (KK+1)-th smallest value INCLUDING the
    // self point (self is the global min, so rank KK+1 of all == rank KK of
    // the real neighbors; superset property preserved even under ties). ----
    const unsigned int KT = KK + 1;
    unsigned int c1, less1;
    {
        unsigned int h[8], s = 0;
        #pragma unroll
        for (int j = 0; j < 8; ++j) { h[j] = hist[wid][lane * 8 + j]; s += h[j]; }
        unsigned int incl = s;
        #pragma unroll
        for (int o = 1; o < 32; o <<= 1) {
            unsigned int x = __shfl_up_sync(FULLMASK, incl, o);
            if (lane >= o) incl += x;
        }
        const unsigned int e   = incl - s;
        const bool         has = (e < KT && KT <= incl);   // exactly one lane
        unsigned int cc = 0, ll = 0;
        if (has) {
            unsigned int cum = e;
            #pragma unroll
            for (int j = 0; j < 8; ++j) {
                if (KT <= cum + h[j]) { cc = lane * 8 + j; ll = cum; break; }
                cum += h[j];
            }
        }
        const int srcl = __ffs(__ballot_sync(FULLMASK, has)) - 1;
        c1    = __shfl_sync(FULLMASK, cc, srcl);
        less1 = __shfl_sync(FULLMASK, ll, srcl);
    }

    // ---- Pass B (fused): compact ALL items with exponent <= c1 into cand as
    // d^2-keys (u64: (d2bits<<10)|idx) AND build the level-2 histogram (next
    // 8 mantissa bits) for exponent == c1. Predicate-free distances. ----
    #pragma unroll
    for (int j = 0; j < 8; ++j) hist[wid][lane * 8 + j] = 0;
    __syncwarp();
    unsigned int cnt = 0;
    #pragma unroll 4
    for (int j = 0; j < 16; ++j) {
        const int    q  = lane + 32 * j;
        const float4 p  = s4loc[q];
        const int    t0 = 2 * q;
        unsigned int v0, v1;
        D2BITS(p.x, p.y, v0);
        D2BITS(p.z, p.w, v1);

        const unsigned int e0 = v0 >> 23;
        if (e0 == c1) atomicAdd(&hist[wid][(v0 >> 15) & 0xFFu], 1u);
        bool         sel = (e0 <= c1);
        unsigned int msk = __ballot_sync(FULLMASK, sel);
        if (sel) {
            unsigned int pos = cnt + __popc(msk & ((1u << lane) - 1u));
            if (pos < CAND_CAP)
                cand[wid][pos] = ((unsigned long long)v0 << 10) | (unsigned)t0;
        }
        cnt += __popc(msk);

        const unsigned int e1 = v1 >> 23;
        if (e1 == c1) atomicAdd(&hist[wid][(v1 >> 15) & 0xFFu], 1u);
        sel = (e1 <= c1);
        msk = __ballot_sync(FULLMASK, sel);
        if (sel) {
            unsigned int pos = cnt + __popc(msk & ((1u << lane) - 1u));
            if (pos < CAND_CAP)
                cand[wid][pos] = ((unsigned long long)v1 << 10)
                                 | (unsigned)(t0 + 1);
        }
        cnt += __popc(msk);
    }
    const unsigned int mc = min(cnt, (unsigned)CAND_CAP);
    __syncwarp();

    // ---- Level-2 cutoff -> 16-bit prefix P (rank KT within the combined
    // multiset); +1 sub-bin guard band captures every sqrt-rounding tie at
    // the boundary. ----
    unsigned int Pp1;
    {
        const unsigned int K2 = KT - less1;                // >= 1
        unsigned int h[8], s = 0;
        #pragma unroll
        for (int j = 0; j < 8; ++j) { h[j] = hist[wid][lane * 8 + j]; s += h[j]; }
        unsigned int incl = s;
        #pragma unroll
        for (int o = 1; o < 32; o <<= 1) {
            unsigned int x = __shfl_up_sync(FULLMASK, incl, o);
            if (lane >= o) incl += x;
        }
        const unsigned int e   = incl - s;
        const bool         has = (e < K2 && K2 <= incl);
        unsigned int pp = 0;
        if (has) {
            unsigned int cum = e;
            #pragma unroll
            for (int j = 0; j < 8; ++j) {
                if (K2 <= cum + h[j]) { pp = (c1 << 8) | (lane * 8 + j); break; }
                cum += h[j];
            }
        }
        const int srcl = __ffs(__ballot_sync(FULLMASK, has)) - 1;
        Pp1 = __shfl_sync(FULLMASK, pp, srcl) + 1;
    }

    // ---- In-place filter over the candidate buffer (~mc/32 iterations):
    // keep prefix <= Pp1 AND idx != i (drops the self point exactly once),
    // sqrt survivors, rewrite as the exact jax ordering key (bits(d)<<10)|idx
    // (ties break to lower index like lax.top_k). Safe in-place: ballot
    // converges the warp after all reads; writes never pass read frontier. ----
    unsigned int m = 0;
    for (unsigned int q0 = 0; q0 < mc; q0 += 32) {
        const unsigned int q = q0 + lane;
        unsigned long long key = 0;
        unsigned int v = 0;
        bool sel = false;
        if (q < mc) {
            key = cand[wid][q];
            v   = (unsigned int)(key >> 10);
            sel = ((v >> 15) <= Pp1) && ((unsigned)(key & 1023u) != (unsigned)i);
        }
        const unsigned int msk = __ballot_sync(FULLMASK, sel);
        if (sel) {
            float d = __fsqrt_rn(__uint_as_float(v));      // IEEE rn sqrt
            cand[wid][m + __popc(msk & ((1u << lane) - 1u))] =
                ((unsigned long long)__float_as_uint(d) << 10)
                | (unsigned)(key & 1023u);
        }
        m += __popc(msk);
    }
    __syncwarp();

    // ---- Rank-select: keys unique (idx in low bits) -> ranks are a
    // permutation; broadcast-LDS counting loop, no sort, no barriers. ----
    for (unsigned int q = lane; q < m; q += 32) {
        const unsigned long long mykey = cand[wid][q];
        unsigned int rk = 0;
        #pragma unroll 4
        for (unsigned int t = 0; t < m; ++t)
            rk += (cand[wid][t] < mykey);
        if (rk < KK) {
            sdist[wid][rk] = __uint_as_float((unsigned int)(mykey >> 10));
            snbr [wid][rk] = (unsigned int)(mykey & 1023u);
        }
    }
    __syncwarp();

    // W/bias loads issued before the edge_index stores so their L2 latency
    // hides under those stores.
    const float4 w4 = __ldg(reinterpret_cast<const float4*>(W) + lane);
    const float4 b4 = __ldg(reinterpret_cast<const float4*>(bias) + lane);

    // ---- edge_index (coalesced, as float). ----
    {
        float* srcp = out + X_ELEMS;
        float* dstp = srcp + E_ELEMS;
        const long long e0 = (long long)node * KK;
        #pragma unroll
        for (int s = lane; s < KK; s += 32) {
            srcp[e0 + s] = (float)node;
            dstp[e0 + s] = (float)(b * NN + (int)snbr[wid][s]);
        }
    }

    // ---- edge_emb[e, :] = dist_e * W + bias; 50 streaming STG.128 rows. ----
    float4* emb = reinterpret_cast<float4*>(out + X_ELEMS + 2LL * E_ELEMS);
    const long long base = (long long)node * KK;
    #pragma unroll 10
    for (int s = 0; s < KK; ++s) {
        const float dd = sdist[wid][s];
        float4 v;
        v.x = fmaf(dd, w4.x, b4.x);
        v.y = fmaf(dd, w4.y, b4.y);
        v.z = fmaf(dd, w4.z, b4.z);
        v.w = fmaf(dd, w4.w, b4.w);
        __stcs(emb + (base + s) * 32 + lane, v);
    }
    #undef D2BITS
}

extern "C" void kernel_launch(void* const* d_in, const int* in_sizes, int n_in,
                              void* d_out, int out_size)
{
    const float* locs = (const float*)d_in[0];   // [16, 1000, 2]
    const float* xin  = (const float*)d_in[1];   // [16, 1000, 128]
    const float* W    = (const float*)d_in[2];   // [1, 128]
    const float* bias = (const float*)d_in[3];   // [128]
    float* out = (float*)d_out;

    tsp_topk_kernel<<<(BB * NN) / WPB, NTHREADS, 0, 0>>>(locs, xin, W, bias, out);
}